// round 4
// baseline (speedup 1.0000x reference)
#include <cuda_runtime.h>

#define BATCH 4
#define NPTS  4096
#define DIM   128
#define TM    64
#define TN    64
#define RATIO 0.85f
#define EPSV  1e-8f

// Scratch (allocation-free rule: __device__ globals)
__device__ float g_v1[BATCH * NPTS];
__device__ float g_v2[BATCH * NPTS];
__device__ int   g_i1[BATCH * NPTS];

// ---------------------------------------------------------------------------
// Kernel 1: tiled fp32 GEMM with fused running top-2 per desc1 row.
// Block = 64 desc1 rows (one batch), loops over all 4096 desc2 rows in 64-col
// tiles. 256 threads as 16x16, each computing a 4x4 microtile.
// As/Bs stored transposed [k][r|c] with +4 float pad -> conflict-free frags.
// ---------------------------------------------------------------------------
__global__ __launch_bounds__(256) void sim_top2_kernel(const float* __restrict__ d1,
                                                       const float* __restrict__ d2) {
    __shared__ float As[DIM][TM + 4];
    __shared__ float Bs[DIM][TN + 4];

    const int b    = blockIdx.y;
    const int row0 = blockIdx.x * TM;
    const float* A  = d1 + (size_t)b * NPTS * DIM;
    const float* Bm = d2 + (size_t)b * NPTS * DIM;

    const int tid = threadIdx.x;
    const int tx  = tid & 15;       // column group
    const int ty  = tid >> 4;       // row group

    // Load A tile once, transposed: As[k][r]. c-fastest mapping -> conflict-free STS.
    for (int i = tid; i < (DIM / 4) * TM; i += 256) {
        int r  = i % TM;
        int k4 = i / TM;
        float4 v = *(const float4*)(A + (size_t)(row0 + r) * DIM + 4 * k4);
        As[4 * k4 + 0][r] = v.x;
        As[4 * k4 + 1][r] = v.y;
        As[4 * k4 + 2][r] = v.z;
        As[4 * k4 + 3][r] = v.w;
    }

    float t1[4], t2[4];
    int   i1[4];
#pragma unroll
    for (int i = 0; i < 4; i++) { t1[i] = -1e30f; t2[i] = -1e30f; i1[i] = 0; }

    for (int c0 = 0; c0 < NPTS; c0 += TN) {
        __syncthreads();  // Bs reuse barrier (also covers first-iter As visibility)
        for (int i = tid; i < (DIM / 4) * TN; i += 256) {
            int c  = i % TN;
            int k4 = i / TN;
            float4 v = *(const float4*)(Bm + (size_t)(c0 + c) * DIM + 4 * k4);
            Bs[4 * k4 + 0][c] = v.x;
            Bs[4 * k4 + 1][c] = v.y;
            Bs[4 * k4 + 2][c] = v.z;
            Bs[4 * k4 + 3][c] = v.w;
        }
        __syncthreads();

        float acc[4][4];
#pragma unroll
        for (int i = 0; i < 4; i++)
#pragma unroll
            for (int j = 0; j < 4; j++) acc[i][j] = 0.f;

#pragma unroll 16
        for (int k = 0; k < DIM; k++) {
            float av[4], bv[4];
            *(float4*)av = *(const float4*)&As[k][4 * ty];
            *(float4*)bv = *(const float4*)&Bs[k][4 * tx];
#pragma unroll
            for (int i = 0; i < 4; i++)
#pragma unroll
                for (int j = 0; j < 4; j++)
                    acc[i][j] = fmaf(av[i], bv[j], acc[i][j]);
        }

        // Fused running top-2. Per-thread columns are visited in ascending
        // global index order, so strict '>' keeps the lowest index on ties
        // (matching jax.lax.top_k).
#pragma unroll
        for (int i = 0; i < 4; i++) {
#pragma unroll
            for (int j = 0; j < 4; j++) {
                float v = acc[i][j];
                int   c = c0 + 4 * tx + j;
                if (v > t1[i]) { t2[i] = t1[i]; t1[i] = v; i1[i] = c; }
                else if (v > t2[i]) { t2[i] = v; }
            }
        }
    }

    // Merge 16 per-thread partial top-2s per row. Reuse As smem.
    __syncthreads();
    float* sv1 = (float*)As;             // TM*16 floats
    float* sv2 = sv1 + TM * 16;
    int*   si1 = (int*)(sv2 + TM * 16);

#pragma unroll
    for (int i = 0; i < 4; i++) {
        int r = 4 * ty + i;
        sv1[r * 16 + tx] = t1[i];
        sv2[r * 16 + tx] = t2[i];
        si1[r * 16 + tx] = i1[i];
    }
    __syncthreads();

    if (tid < TM) {
        int r = tid;
        float V1 = -1e30f, V2 = -1e30f;
        int   I1 = 0;
        for (int t = 0; t < 16; t++) {
            float v1c = sv1[r * 16 + t];
            float v2c = sv2[r * 16 + t];
            int   ic  = si1[r * 16 + t];
            if (v1c > V1 || (v1c == V1 && ic < I1)) {
                V2 = fmaxf(V1, v2c);
                V1 = v1c;
                I1 = ic;
            } else {
                V2 = fmaxf(V2, v1c);  // v2c <= v1c, so v1c is the only new V2 candidate
            }
        }
        int gi = b * NPTS + row0 + r;
        g_v1[gi] = V1;
        g_v2[gi] = V2;
        g_i1[gi] = I1;
    }
}

// ---------------------------------------------------------------------------
// Kernel 2: per-batch stable two-bucket compaction (valid first, then invalid,
// both in original order; invalid slots written as zeros per the keep mask).
// One 1024-thread block per batch, 4 contiguous elements per thread.
// ---------------------------------------------------------------------------
__global__ __launch_bounds__(1024) void compact_kernel(int* __restrict__ out) {
    const int b    = blockIdx.x;
    const int tid  = threadIdx.x;
    const int base = b * NPTS;

    bool m[4];
    int  d[4];
    int  cl = 0;
#pragma unroll
    for (int j = 0; j < 4; j++) {
        int g = tid * 4 + j;
        float v1 = g_v1[base + g];
        float v2 = g_v2[base + g];
        m[j] = (v1 / (v2 + EPSV)) < RATIO;
        d[j] = g_i1[base + g];
        cl += m[j];
    }

    const int lane = tid & 31;
    const int warp = tid >> 5;
    int inc = cl;
#pragma unroll
    for (int o = 1; o < 32; o <<= 1) {
        int y = __shfl_up_sync(0xffffffffu, inc, o);
        if (lane >= o) inc += y;
    }

    __shared__ int wsum[32];
    __shared__ int woff[32];
    __shared__ int totalS;
    if (lane == 31) wsum[warp] = inc;
    __syncthreads();
    if (tid == 0) {
        int acc = 0;
        for (int w = 0; w < 32; w++) { woff[w] = acc; acc += wsum[w]; }
        totalS = acc;
    }
    __syncthreads();

    const int cnt = totalS;
    int vb = woff[warp] + (inc - cl);  // #valid strictly before this thread's first elem

    int2* o2 = (int2*)out + b * NPTS;
#pragma unroll
    for (int j = 0; j < 4; j++) {
        int g = tid * 4 + j;
        int  pos;
        int2 val;
        if (m[j]) { pos = vb; val = make_int2(g, d[j]); vb++; }
        else      { pos = cnt + (g - vb); val = make_int2(0, 0); }
        o2[pos] = val;
    }
}

extern "C" void kernel_launch(void* const* d_in, const int* in_sizes, int n_in,
                              void* d_out, int out_size) {
    const float* d1 = (const float*)d_in[0];
    const float* d2 = (const float*)d_in[1];
    (void)in_sizes; (void)n_in; (void)out_size;

    dim3 grid(NPTS / TM, BATCH);
    sim_top2_kernel<<<grid, 256>>>(d1, d2);
    compact_kernel<<<BATCH, 1024>>>((int*)d_out);
}

// round 6
// speedup vs baseline: 1.6100x; 1.6100x over previous
#include <cuda_runtime.h>
#include <cstdint>

#define BATCH 4
#define NPTS  4096
#define DIM   128
#define TM    128          // desc1 rows per CTA
#define TN    64           // desc2 rows per col-tile
#define NTILES (NPTS / TN) // 64
#define SSTR  132          // smem row stride in floats (DIM + 4 pad)
#define RATIO 0.85f
#define EPSV  1e-8f

// Scratch (allocation-free rule: __device__ globals)
__device__ float g_v1[BATCH * NPTS];
__device__ float g_v2[BATCH * NPTS];
__device__ int   g_i1[BATCH * NPTS];

// dynamic smem layout in floats
#define A_HI 0
#define A_LO (TM * SSTR)
#define B_HI (2 * TM * SSTR)
#define B_LO (2 * TM * SSTR + TN * SSTR)
#define SM_FLOATS (2 * TM * SSTR + 2 * TN * SSTR)   // 50688 floats = 202752 B

__device__ __forceinline__ uint32_t f2tf32(float x) {
    uint32_t r;
    asm("cvt.rna.tf32.f32 %0, %1;" : "=r"(r) : "f"(x));
    return r;
}

__device__ __forceinline__ void mma_tf32(float* c, const uint32_t* a, const uint32_t* b) {
    asm volatile(
        "mma.sync.aligned.m16n8k8.row.col.f32.tf32.tf32.f32 "
        "{%0,%1,%2,%3}, {%4,%5,%6,%7}, {%8,%9}, {%0,%1,%2,%3};"
        : "+f"(c[0]), "+f"(c[1]), "+f"(c[2]), "+f"(c[3])
        : "r"(a[0]), "r"(a[1]), "r"(a[2]), "r"(a[3]), "r"(b[0]), "r"(b[1]));
}

// Split a float4 into tf32 hi/lo and store both as float4 into smem.
__device__ __forceinline__ void split_store(float* hi_p, float* lo_p, float4 v) {
    uint4 h, l;
    h.x = f2tf32(v.x); h.y = f2tf32(v.y); h.z = f2tf32(v.z); h.w = f2tf32(v.w);
    l.x = f2tf32(v.x - __uint_as_float(h.x));
    l.y = f2tf32(v.y - __uint_as_float(h.y));
    l.z = f2tf32(v.z - __uint_as_float(h.z));
    l.w = f2tf32(v.w - __uint_as_float(h.w));
    *(uint4*)hi_p = h;
    *(uint4*)lo_p = l;
}

// ---------------------------------------------------------------------------
// Kernel 1: 3xTF32 mma.sync GEMM (sim = D1 * D2^T) with fused per-row top-2.
// 256 threads = 8 warps (4 m-groups x 2 n-groups), warp tile 32x32.
// ---------------------------------------------------------------------------
__global__ __launch_bounds__(256, 1) void sim_top2_mma(const float* __restrict__ d1,
                                                       const float* __restrict__ d2) {
    extern __shared__ float sm[];

    const int tid  = threadIdx.x;
    const int wid  = tid >> 5;
    const int lane = tid & 31;
    const int g    = lane >> 2;     // group id (row within fragment)
    const int tig  = lane & 3;      // thread in group (k / col pair)
    const int wm   = wid & 3;       // warp m-group: rows wm*32..+31
    const int wn   = wid >> 2;      // warp n-group: cols wn*32..+31

    const int b    = blockIdx.y;
    const int row0 = blockIdx.x * TM;

    // ---- load + split A tile [TM x DIM] (once) ----
    {
        const float4* A = (const float4*)(d1 + (size_t)b * NPTS * DIM);
        for (int i = tid; i < TM * (DIM / 4); i += 256) {
            int row = i >> 5, k4 = i & 31;
            float4 v = A[(size_t)(row0 + row) * (DIM / 4) + k4];
            split_store(sm + A_HI + row * SSTR + 4 * k4,
                        sm + A_LO + row * SSTR + 4 * k4, v);
        }
    }

    // warp-local smem bases
    const float* As_hi = sm + A_HI + (wm * 32) * SSTR;
    const float* As_lo = sm + A_LO + (wm * 32) * SSTR;
    const float* Bs_hi = sm + B_HI + (wn * 32) * SSTR;
    const float* Bs_lo = sm + B_LO + (wn * 32) * SSTR;

    float t1[4], t2[4];
    int   i1[4];
#pragma unroll
    for (int s = 0; s < 4; s++) { t1[s] = -1e30f; t2[s] = -1e30f; i1[s] = 0; }

    const float4* Bm = (const float4*)(d2 + (size_t)b * NPTS * DIM);

    for (int t = 0; t < NTILES; t++) {
        const int c0 = t * TN;

        __syncthreads();  // previous tile's B readers done (also covers A store on t=0)
        for (int i = tid; i < TN * (DIM / 4); i += 256) {
            int row = i >> 5, k4 = i & 31;
            float4 v = Bm[(size_t)(c0 + row) * (DIM / 4) + k4];
            split_store(sm + B_HI + row * SSTR + 4 * k4,
                        sm + B_LO + row * SSTR + 4 * k4, v);
        }
        __syncthreads();

        float acc[2][4][4];
#pragma unroll
        for (int mt = 0; mt < 2; mt++)
#pragma unroll
            for (int nt = 0; nt < 4; nt++)
#pragma unroll
                for (int c = 0; c < 4; c++) acc[mt][nt][c] = 0.f;

#pragma unroll 4
        for (int ks = 0; ks < 16; ks++) {
            const int k0 = ks * 8;

            // B fragments: b0 = B2[col=nt*8+g][k0+tig], b1 = +4 in k
            uint32_t bh[4][2], bl[4][2];
#pragma unroll
            for (int nt = 0; nt < 4; nt++) {
                int off = (nt * 8 + g) * SSTR + k0 + tig;
                bh[nt][0] = __float_as_uint(Bs_hi[off]);
                bh[nt][1] = __float_as_uint(Bs_hi[off + 4]);
                bl[nt][0] = __float_as_uint(Bs_lo[off]);
                bl[nt][1] = __float_as_uint(Bs_lo[off + 4]);
            }

#pragma unroll
            for (int mt = 0; mt < 2; mt++) {
                int off = (mt * 16 + g) * SSTR + k0 + tig;
                uint32_t ah[4], al[4];
                ah[0] = __float_as_uint(As_hi[off]);
                ah[1] = __float_as_uint(As_hi[off + 8 * SSTR]);
                ah[2] = __float_as_uint(As_hi[off + 4]);
                ah[3] = __float_as_uint(As_hi[off + 8 * SSTR + 4]);
                al[0] = __float_as_uint(As_lo[off]);
                al[1] = __float_as_uint(As_lo[off + 8 * SSTR]);
                al[2] = __float_as_uint(As_lo[off + 4]);
                al[3] = __float_as_uint(As_lo[off + 8 * SSTR + 4]);
#pragma unroll
                for (int nt = 0; nt < 4; nt++) {
                    mma_tf32(acc[mt][nt], ah, bh[nt]);   // hi*hi
                    mma_tf32(acc[mt][nt], ah, bl[nt]);   // hi*lo
                    mma_tf32(acc[mt][nt], al, bh[nt]);   // lo*hi
                }
            }
        }

        // Fused running top-2. slot = mt*2 + h owns row (mt*16 + h*8 + g) within
        // the warp's 32 rows. Columns ascend (nt, then j), tiles ascend -> strict
        // '>' keeps lowest index on ties (jax.lax.top_k semantics).
#pragma unroll
        for (int mt = 0; mt < 2; mt++) {
#pragma unroll
            for (int h = 0; h < 2; h++) {
                const int s = mt * 2 + h;
#pragma unroll
                for (int nt = 0; nt < 4; nt++) {
#pragma unroll
                    for (int j = 0; j < 2; j++) {
                        float v = acc[mt][nt][h * 2 + j];
                        int   c = c0 + wn * 32 + nt * 8 + 2 * tig + j;
                        if (v > t1[s])      { t2[s] = t1[s]; t1[s] = v; i1[s] = c; }
                        else if (v > t2[s]) { t2[s] = v; }
                    }
                }
            }
        }
    }

    // ---- final merge: 8 partials per row (2 warp_n x 4 tig), reuse smem ----
    __syncthreads();
    float* mv1 = sm;                  // [128][8]
    float* mv2 = sm + 1024;
    int*   mi1 = (int*)(sm + 2048);

#pragma unroll
    for (int s = 0; s < 4; s++) {
        int r = wm * 32 + s * 8 + g;
        int e = wn * 4 + tig;
        mv1[r * 8 + e] = t1[s];
        mv2[r * 8 + e] = t2[s];
        mi1[r * 8 + e] = i1[s];
    }
    __syncthreads();

    if (tid < TM) {
        float V1 = -1e30f, V2 = -1e30f;
        int   I1 = 0;
#pragma unroll
        for (int e = 0; e < 8; e++) {
            float v1c = mv1[tid * 8 + e];
            float v2c = mv2[tid * 8 + e];
            int   ic  = mi1[tid * 8 + e];
            if (v1c > V1 || (v1c == V1 && ic < I1)) {
                V2 = fmaxf(V1, v2c);
                V1 = v1c;
                I1 = ic;
            } else {
                V2 = fmaxf(V2, v1c);   // v2c <= v1c, so v1c is the only new V2 candidate
            }
        }
        int gi = b * NPTS + row0 + tid;
        g_v1[gi] = V1;
        g_v2[gi] = V2;
        g_i1[gi] = I1;
    }
}

// ---------------------------------------------------------------------------
// Kernel 2: per-batch stable two-bucket compaction (unchanged, ~7us).
// ---------------------------------------------------------------------------
__global__ __launch_bounds__(1024) void compact_kernel(int* __restrict__ out) {
    const int b    = blockIdx.x;
    const int tid  = threadIdx.x;
    const int base = b * NPTS;

    bool m[4];
    int  d[4];
    int  cl = 0;
#pragma unroll
    for (int j = 0; j < 4; j++) {
        int g = tid * 4 + j;
        float v1 = g_v1[base + g];
        float v2 = g_v2[base + g];
        m[j] = (v1 / (v2 + EPSV)) < RATIO;
        d[j] = g_i1[base + g];
        cl += m[j];
    }

    const int lane = tid & 31;
    const int warp = tid >> 5;
    int inc = cl;
#pragma unroll
    for (int o = 1; o < 32; o <<= 1) {
        int y = __shfl_up_sync(0xffffffffu, inc, o);
        if (lane >= o) inc += y;
    }

    __shared__ int wsum[32];
    __shared__ int woff[32];
    __shared__ int totalS;
    if (lane == 31) wsum[warp] = inc;
    __syncthreads();
    if (tid == 0) {
        int acc = 0;
        for (int w = 0; w < 32; w++) { woff[w] = acc; acc += wsum[w]; }
        totalS = acc;
    }
    __syncthreads();

    const int cnt = totalS;
    int vb = woff[warp] + (inc - cl);

    int2* o2 = (int2*)out + b * NPTS;
#pragma unroll
    for (int j = 0; j < 4; j++) {
        int g = tid * 4 + j;
        int  pos;
        int2 val;
        if (m[j]) { pos = vb; val = make_int2(g, d[j]); vb++; }
        else      { pos = cnt + (g - vb); val = make_int2(0, 0); }
        o2[pos] = val;
    }
}

extern "C" void kernel_launch(void* const* d_in, const int* in_sizes, int n_in,
                              void* d_out, int out_size) {
    const float* d1 = (const float*)d_in[0];
    const float* d2 = (const float*)d_in[1];
    (void)in_sizes; (void)n_in; (void)out_size;

    cudaFuncSetAttribute(sim_top2_mma, cudaFuncAttributeMaxDynamicSharedMemorySize,
                         SM_FLOATS * (int)sizeof(float));

    dim3 grid(NPTS / TM, BATCH);
    sim_top2_mma<<<grid, 256, SM_FLOATS * sizeof(float)>>>(d1, d2);
    compact_kernel<<<BATCH, 1024>>>((int*)d_out);
}